// round 9
// baseline (speedup 1.0000x reference)
#include <cuda_runtime.h>

#define H 64
#define NMAX 50000
#define EMAX 800000

typedef unsigned long long u64;

// ---- static scratch (no allocations allowed) ----
__device__ float g_h[NMAX * H];     // encoder output
__device__ float g_hw[NMAX * H];    // (h @ W[l]) * dinv[node]
__device__ float g_aggA[NMAX * H];  // ping
__device__ float g_aggB[NMAX * H];  // pong
__device__ float g_dinv[NMAX];
__device__ int   g_cnt[NMAX];       // zero-init; self-cleared each call
__device__ int   g_off[NMAX + 1];
__device__ int   g_cur[NMAX];
__device__ int   g_csr[EMAX];
__device__ int   g_part[2048];      // per-block partial sums

// ---- software grid barrier (self-resetting; zero-init) ----
__device__ volatile unsigned g_arr[16];
__device__ volatile unsigned g_dep[16];

__device__ __forceinline__ void gsync(int p, unsigned nb) {
    __syncthreads();
    if (threadIdx.x == 0) {
        __threadfence();
        atomicAdd((unsigned*)&g_arr[p], 1u);
        while (g_arr[p] < nb) __nanosleep(64);
        __threadfence();
        unsigned d = atomicAdd((unsigned*)&g_dep[p], 1u) + 1;
        if (d == nb) {              // last one out resets for next call
            g_arr[p] = 0;
            __threadfence();
            g_dep[p] = 0;
        }
    }
    __syncthreads();
}

// packed f32x2 helpers
__device__ __forceinline__ void ffma2(u64& d, u64 a, u64 b) {
    asm("fma.rn.f32x2 %0, %1, %2, %3;" : "=l"(d) : "l"(a), "l"(b), "l"(d));
}
__device__ __forceinline__ u64 pack2(float v) {
    u64 r; unsigned u = __float_as_uint(v);
    asm("mov.b64 %0, {%1, %1};" : "=l"(r) : "r"(u));
    return r;
}
union F4U2 { float4 f; u64 u[2]; };

// block-wide exclusive scan of one int per thread (256 thr); sS = 32-int scratch
__device__ __forceinline__ int block_excl_scan(int v, int* sS, int* total) {
    int t = threadIdx.x, lane = t & 31, w = t >> 5;
    int x = v;
#pragma unroll
    for (int o = 1; o < 32; o <<= 1) {
        int y = __shfl_up_sync(0xffffffffu, x, o);
        if (lane >= o) x += y;
    }
    if (lane == 31) sS[w] = x;
    __syncthreads();
    if (w == 0) {
        int s = (lane < 8) ? sS[lane] : 0;
#pragma unroll
        for (int o = 1; o < 8; o <<= 1) {
            int y = __shfl_up_sync(0xffffffffu, s, o);
            if (lane >= o) s += y;
        }
        if (lane < 8) sS[lane] = s;
    }
    __syncthreads();
    int pref = (w > 0) ? sS[w - 1] : 0;
    if (total) *total = sS[7];
    int r = pref + x - v;
    __syncthreads();
    return r;
}

// ---- gemm phase: g_hw = (preop(in) @ W) * dinv ; tiles of 64 nodes ----
__device__ __forceinline__ void gemm_phase(
    const float* __restrict__ in, const float* __restrict__ W,
    const float* __restrict__ preb, int hasPre, int N,
    float* sIn /*64*65 floats*/, int nb)
{
    int t = threadIdx.x;
    int tiles = (N + 63) / 64;
    for (int tile = blockIdx.x; tile < tiles; tile += nb) {
        __syncthreads();
        // load 64x64 input tile (1024 float4 by 256 threads x4)
#pragma unroll
        for (int r = 0; r < 4; r++) {
            int lin = t + r * 256;
            int n = lin >> 4;
            int c4 = (lin & 15) * 4;
            int i = tile * 64 + n;
            float4 v = make_float4(0.f, 0.f, 0.f, 0.f);
            if (i < N) v = *(const float4*)&in[i * 64 + c4];
            if (hasPre) {
                v.x = fmaxf(v.x + preb[c4 + 0], 0.f);
                v.y = fmaxf(v.y + preb[c4 + 1], 0.f);
                v.z = fmaxf(v.z + preb[c4 + 2], 0.f);
                v.w = fmaxf(v.w + preb[c4 + 3], 0.f);
            }
            float* s = &sIn[n * 65 + c4];
            s[0] = v.x; s[1] = v.y; s[2] = v.z; s[3] = v.w;
        }
        __syncthreads();

        int n = t >> 2;
        int q = t & 3;
        u64 acc[8];
#pragma unroll
        for (int j = 0; j < 8; j++) acc[j] = 0ull;

        const float4* __restrict__ Wq = (const float4*)(W + q * 16);
#pragma unroll 8
        for (int k = 0; k < 64; k++) {
            u64 h = pack2(sIn[n * 65 + k]);
            const float4* wp = Wq + k * 16;
            F4U2 w0, w1, w2, w3;
            w0.f = __ldg(wp); w1.f = __ldg(wp + 1);
            w2.f = __ldg(wp + 2); w3.f = __ldg(wp + 3);
            ffma2(acc[0], h, w0.u[0]); ffma2(acc[1], h, w0.u[1]);
            ffma2(acc[2], h, w1.u[0]); ffma2(acc[3], h, w1.u[1]);
            ffma2(acc[4], h, w2.u[0]); ffma2(acc[5], h, w2.u[1]);
            ffma2(acc[6], h, w3.u[0]); ffma2(acc[7], h, w3.u[1]);
        }

        int i = tile * 64 + n;
        if (i < N) {
            float da = g_dinv[i];
            float* p = &g_hw[i * 64 + q * 16];
#pragma unroll
            for (int r = 0; r < 4; r++) {
                F4U2 o; o.u[0] = acc[2*r]; o.u[1] = acc[2*r+1];
                o.f.x *= da; o.f.y *= da; o.f.z *= da; o.f.w *= da;
                *(float4*)&p[r * 4] = o.f;
            }
        }
    }
}

// ---- aggregate phase: agg_i = dinv_i * (hws_i + sum hws[src]) ----
__device__ __forceinline__ void agg_phase(float* __restrict__ agg, int N,
                                          unsigned T, unsigned gid)
{
    for (unsigned u = gid; u < (unsigned)(N * 16); u += T) {
        int i = u >> 4;
        int c4 = (u & 15) * 4;

        float4 acc = *(const float4*)&g_hw[i * 64 + c4];
        int j = g_off[i];
        int end = g_off[i + 1];

        while (j + 8 <= end) {
            int s0 = g_csr[j+0], s1 = g_csr[j+1], s2 = g_csr[j+2], s3 = g_csr[j+3];
            int s4 = g_csr[j+4], s5 = g_csr[j+5], s6 = g_csr[j+6], s7 = g_csr[j+7];
            float4 v0 = __ldcg((const float4*)&g_hw[s0 * 64 + c4]);
            float4 v1 = __ldcg((const float4*)&g_hw[s1 * 64 + c4]);
            float4 v2 = __ldcg((const float4*)&g_hw[s2 * 64 + c4]);
            float4 v3 = __ldcg((const float4*)&g_hw[s3 * 64 + c4]);
            float4 v4 = __ldcg((const float4*)&g_hw[s4 * 64 + c4]);
            float4 v5 = __ldcg((const float4*)&g_hw[s5 * 64 + c4]);
            float4 v6 = __ldcg((const float4*)&g_hw[s6 * 64 + c4]);
            float4 v7 = __ldcg((const float4*)&g_hw[s7 * 64 + c4]);
            acc.x += ((v0.x+v1.x)+(v2.x+v3.x)) + ((v4.x+v5.x)+(v6.x+v7.x));
            acc.y += ((v0.y+v1.y)+(v2.y+v3.y)) + ((v4.y+v5.y)+(v6.y+v7.y));
            acc.z += ((v0.z+v1.z)+(v2.z+v3.z)) + ((v4.z+v5.z)+(v6.z+v7.z));
            acc.w += ((v0.w+v1.w)+(v2.w+v3.w)) + ((v4.w+v5.w)+(v6.w+v7.w));
            j += 8;
        }
        if (j + 4 <= end) {
            int s0 = g_csr[j+0], s1 = g_csr[j+1], s2 = g_csr[j+2], s3 = g_csr[j+3];
            float4 v0 = __ldcg((const float4*)&g_hw[s0 * 64 + c4]);
            float4 v1 = __ldcg((const float4*)&g_hw[s1 * 64 + c4]);
            float4 v2 = __ldcg((const float4*)&g_hw[s2 * 64 + c4]);
            float4 v3 = __ldcg((const float4*)&g_hw[s3 * 64 + c4]);
            acc.x += (v0.x+v1.x)+(v2.x+v3.x);
            acc.y += (v0.y+v1.y)+(v2.y+v3.y);
            acc.z += (v0.z+v1.z)+(v2.z+v3.z);
            acc.w += (v0.w+v1.w)+(v2.w+v3.w);
            j += 4;
        }
        if (j + 2 <= end) {
            int s0 = g_csr[j], s1 = g_csr[j+1];
            float4 v0 = __ldcg((const float4*)&g_hw[s0 * 64 + c4]);
            float4 v1 = __ldcg((const float4*)&g_hw[s1 * 64 + c4]);
            acc.x += v0.x+v1.x; acc.y += v0.y+v1.y;
            acc.z += v0.z+v1.z; acc.w += v0.w+v1.w;
            j += 2;
        }
        if (j < end) {
            float4 v0 = __ldcg((const float4*)&g_hw[g_csr[j] * 64 + c4]);
            acc.x += v0.x; acc.y += v0.y; acc.z += v0.z; acc.w += v0.w;
        }

        float dv = g_dinv[i];
        *(float4*)&agg[i * 64 + c4] =
            make_float4(acc.x * dv, acc.y * dv, acc.z * dv, acc.w * dv);
    }
}

// =================== THE persistent megakernel ===================
__global__ void __launch_bounds__(256, 3) persistent_k(
    const float* __restrict__ x, const int* __restrict__ src,
    const int* __restrict__ dst,
    const float* __restrict__ W_enc, const float* __restrict__ b_enc,
    const float* __restrict__ conv_W, const float* __restrict__ conv_b,
    const float* __restrict__ Wd1, const float* __restrict__ bd1,
    const float* __restrict__ Wd2, const float* __restrict__ bd2,
    const float* __restrict__ Wi1, const float* __restrict__ bi1,
    const float* __restrict__ Wi2, const float* __restrict__ bi2,
    float* __restrict__ out, int N, int E, int nb)
{
    __shared__ float sBuf[5120];           // 20KB union
    int* sS = (int*)&sBuf[5088];           // 32-int scan scratch (top of union)

    int t = threadIdx.x;
    int bid = blockIdx.x;
    unsigned T = (unsigned)nb * 256u;
    unsigned gid = (unsigned)bid * 256u + (unsigned)t;

    // ---------- P0: encoder + degree histogram ----------
    for (int i = t; i < 320; i += 256) sBuf[i] = W_enc[i];
    if (t < 64) sBuf[320 + t] = b_enc[t];
    __syncthreads();
    for (unsigned u = gid; u < (unsigned)(N * 16); u += T) {
        int i = u >> 4;
        int c = (u & 15) * 4;
        float xv[5];
#pragma unroll
        for (int f = 0; f < 5; f++) xv[f] = x[i * 5 + f];
        float a0 = sBuf[320+c], a1 = sBuf[320+c+1], a2 = sBuf[320+c+2], a3 = sBuf[320+c+3];
#pragma unroll
        for (int f = 0; f < 5; f++) {
            const float* wr = &sBuf[f * 64 + c];
            a0 += xv[f] * wr[0]; a1 += xv[f] * wr[1];
            a2 += xv[f] * wr[2]; a3 += xv[f] * wr[3];
        }
        float4 o;
        o.x = fmaxf(a0, 0.f); o.y = fmaxf(a1, 0.f);
        o.z = fmaxf(a2, 0.f); o.w = fmaxf(a3, 0.f);
        *(float4*)&g_h[i * 64 + c] = o;
    }
    for (unsigned e = gid; e < (unsigned)E; e += T)
        atomicAdd(&g_cnt[dst[e]], 1);
    gsync(0, nb);

    // ---------- P1: per-block chunk sums ----------
    int chunk = (N + nb - 1) / nb;
    int lo = bid * chunk;
    int hi = min(N, lo + chunk);
    {
        int s = 0;
        for (int i = lo + t; i < hi; i += 256) s += g_cnt[i];
        int tot;
        block_excl_scan(s, sS, &tot);
        if (t == 0) g_part[bid] = tot;
    }
    gsync(1, nb);

    // ---------- P2: block 0 scans the nb partials ----------
    if (bid == 0) {
        int per = (nb + 255) / 256;     // <= 8
        int loc[8];
        int s = 0;
#pragma unroll 8
        for (int r = 0; r < per; r++) {
            int idx = t * per + r;
            int v = (idx < nb) ? g_part[idx] : 0;
            loc[r] = s; s += v;
        }
        int tot;
        int excl = block_excl_scan(s, sS, &tot);
#pragma unroll 8
        for (int r = 0; r < per; r++) {
            int idx = t * per + r;
            if (idx < nb) g_part[idx] = excl + loc[r];
        }
        if (t == 0) g_off[N] = tot;
    }
    gsync(2, nb);

    // ---------- P3: local scan -> off/cur/dinv (+ cnt self-clear) ----------
    {
        int base = g_part[bid];
        int cl = hi - lo;                 // chunk length
        int per = (cl + 255) / 256;       // <= 8
        int loc[8], cvals[8];
        int s = 0;
#pragma unroll 8
        for (int r = 0; r < per; r++) {
            int i = lo + t * per + r;
            int v = (t * per + r < cl) ? g_cnt[i] : 0;
            cvals[r] = v; loc[r] = s; s += v;
        }
        int excl = block_excl_scan(s, sS, nullptr) + base;
#pragma unroll 8
        for (int r = 0; r < per; r++) {
            int i = lo + t * per + r;
            if (t * per + r < cl) {
                int off = excl + loc[r];
                g_cnt[i] = 0;
                g_off[i] = off;
                g_cur[i] = off;
                g_dinv[i] = rsqrtf(1.0f + (float)cvals[r]);
            }
        }
    }
    gsync(3, nb);

    // ---------- P4: gemm layer0 + CSR fill ----------
    gemm_phase(g_h, conv_W, nullptr, 0, N, sBuf, nb);
    for (unsigned e = gid; e < (unsigned)E; e += T) {
        int s = src[e];
        int c = dst[e];
        int pos = atomicAdd(&g_cur[c], 1);
        g_csr[pos] = s;
    }
    gsync(4, nb);

    // ---------- P5..P9: aggregate / gemm alternation ----------
    agg_phase(g_aggA, N, T, gid);
    gsync(5, nb);
    gemm_phase(g_aggA, conv_W + 4096, conv_b, 1, N, sBuf, nb);
    gsync(6, nb);
    agg_phase(g_aggB, N, T, gid);
    gsync(7, nb);
    gemm_phase(g_aggB, conv_W + 8192, conv_b + 64, 1, N, sBuf, nb);
    gsync(8, nb);
    agg_phase(g_aggA, N, T, gid);
    gsync(9, nb);

    // ---------- P10: heads ----------
    {
        float* sWd1 = &sBuf[0];        // 2048
        float* sWi1 = &sBuf[2048];     // 2048
        float* sWd2 = &sBuf[4096];     // 32
        float* sWi2 = &sBuf[4128];     // 32
        float* sbd1 = &sBuf[4160];     // 32
        float* sbi1 = &sBuf[4192];     // 32
        float* scb  = &sBuf[4224];     // 64
        float* sh   = &sBuf[4288];     // 512

        {
            const float4* wd = (const float4*)Wd1;
            const float4* wi = (const float4*)Wi1;
            float4* swd = (float4*)sWd1;
            float4* swi = (float4*)sWi1;
            swd[t] = wd[t]; swd[t + 256] = wd[t + 256];
            swi[t] = wi[t]; swi[t + 256] = wi[t + 256];
        }
        if (t < 32) { sWd2[t] = Wd2[t]; sWi2[t] = Wi2[t]; sbd1[t] = bd1[t]; sbi1[t] = bi1[t]; }
        if (t < 64) scb[t] = conv_b[128 + t];
        __syncthreads();

        int w = t >> 5, lane = t & 31;
        unsigned nwarps = (unsigned)nb * 8u;
        float bd2v = bd2[0], bi2v = bi2[0];
        for (unsigned i = (unsigned)bid * 8u + (unsigned)w; i < (unsigned)N; i += nwarps) {
            float v0 = fmaxf(g_aggA[i * 64 + lane]      + scb[lane],      0.f);
            float v1 = fmaxf(g_aggA[i * 64 + lane + 32] + scb[lane + 32], 0.f);
            sh[w * 64 + lane] = v0;
            sh[w * 64 + lane + 32] = v1;
            __syncwarp();

            float ad = sbd1[lane];
            float ai = sbi1[lane];
#pragma unroll 16
            for (int k = 0; k < 64; k++) {
                float hv = sh[w * 64 + k];
                ad += hv * sWd1[k * 32 + lane];
                ai += hv * sWi1[k * 32 + lane];
            }
            float vd = fmaxf(ad, 0.f) * sWd2[lane];
            float vi = fmaxf(ai, 0.f) * sWi2[lane];
#pragma unroll
            for (int o = 16; o > 0; o >>= 1) {
                vd += __shfl_xor_sync(0xffffffffu, vd, o);
                vi += __shfl_xor_sync(0xffffffffu, vi, o);
            }
            if (lane == 0) {
                out[i]     = vd + bd2v;
                out[N + i] = vi + bi2v;
            }
            __syncwarp();
        }
    }
}

// ---------------- launch ----------------
extern "C" void kernel_launch(void* const* d_in, const int* in_sizes, int n_in,
                              void* d_out, int out_size)
{
    const float* x      = (const float*)d_in[0];
    const int*   ei     = (const int*)d_in[1];     // int32 (JAX x64 off)
    const float* W_enc  = (const float*)d_in[2];
    const float* b_enc  = (const float*)d_in[3];
    const float* conv_W = (const float*)d_in[4];
    const float* conv_b = (const float*)d_in[5];
    const float* W_d1   = (const float*)d_in[6];
    const float* b_d1   = (const float*)d_in[7];
    const float* W_d2   = (const float*)d_in[8];
    const float* b_d2   = (const float*)d_in[9];
    const float* W_i1   = (const float*)d_in[10];
    const float* b_i1   = (const float*)d_in[11];
    const float* W_i2   = (const float*)d_in[12];
    const float* b_i2   = (const float*)d_in[13];
    float* out = (float*)d_out;

    int N = in_sizes[0] / 5;
    int E = in_sizes[1] / 2;
    const int* src = ei;
    const int* dst = ei + E;

    int dev = 0;
    cudaGetDevice(&dev);
    int sms = 148;
    cudaDeviceGetAttribute(&sms, cudaDevAttrMultiProcessorCount, dev);
    int bpm = 0;
    cudaOccupancyMaxActiveBlocksPerMultiprocessor(&bpm, persistent_k, 256, 0);
    if (bpm < 1) bpm = 1;
    if (bpm > 8) bpm = 8;
    int nb = sms * bpm;
    if (nb > 2048) nb = 2048;   // g_part capacity

    persistent_k<<<nb, 256>>>(x, src, dst, W_enc, b_enc, conv_W, conv_b,
                              W_d1, b_d1, W_d2, b_d2,
                              W_i1, b_i1, W_i2, b_i2,
                              out, N, E, nb);
}

// round 10
// speedup vs baseline: 1.1670x; 1.1670x over previous
#include <cuda_runtime.h>

#define H 64
#define NMAX 50000
#define EMAX 800000

typedef unsigned long long u64;

// ---- static scratch (no allocations allowed) ----
__device__ float g_h[NMAX * H];     // encoder output
__device__ float g_hw[NMAX * H];    // (h @ W[l]) * dinv[node]
__device__ float g_aggA[NMAX * H];  // ping
__device__ float g_aggB[NMAX * H];  // pong
__device__ float g_dinv[NMAX];
__device__ int   g_cnt[NMAX];       // zero-init; self-cleared each call
__device__ int   g_off[NMAX + 1];
__device__ int   g_cur[NMAX];
__device__ int   g_csr[EMAX];
__device__ int   g_part[2048];      // per-block partial sums

// ---- software grid barrier (self-resetting; zero-init) ----
__device__ volatile unsigned g_arr[16];
__device__ volatile unsigned g_dep[16];

__device__ __forceinline__ void gsync(int p, unsigned nb) {
    __syncthreads();
    if (threadIdx.x == 0) {
        __threadfence();
        atomicAdd((unsigned*)&g_arr[p], 1u);
        while (g_arr[p] < nb) __nanosleep(64);
        __threadfence();
        unsigned d = atomicAdd((unsigned*)&g_dep[p], 1u) + 1;
        if (d == nb) {              // last one out resets for next call
            g_arr[p] = 0;
            __threadfence();
            g_dep[p] = 0;
        }
    }
    __syncthreads();
}

// packed f32x2 helpers
__device__ __forceinline__ void ffma2(u64& d, u64 a, u64 b) {
    asm("fma.rn.f32x2 %0, %1, %2, %3;" : "=l"(d) : "l"(a), "l"(b), "l"(d));
}
__device__ __forceinline__ u64 pack2(float v) {
    u64 r; unsigned u = __float_as_uint(v);
    asm("mov.b64 %0, {%1, %1};" : "=l"(r) : "r"(u));
    return r;
}
union F4U2 { float4 f; u64 u[2]; };

// block-wide exclusive scan of one int per thread (256 thr); sS = 32-int scratch
__device__ __forceinline__ int block_excl_scan(int v, int* sS, int* total) {
    int t = threadIdx.x, lane = t & 31, w = t >> 5;
    int x = v;
#pragma unroll
    for (int o = 1; o < 32; o <<= 1) {
        int y = __shfl_up_sync(0xffffffffu, x, o);
        if (lane >= o) x += y;
    }
    if (lane == 31) sS[w] = x;
    __syncthreads();
    if (w == 0) {
        int s = (lane < 8) ? sS[lane] : 0;
#pragma unroll
        for (int o = 1; o < 8; o <<= 1) {
            int y = __shfl_up_sync(0xffffffffu, s, o);
            if (lane >= o) s += y;
        }
        if (lane < 8) sS[lane] = s;
    }
    __syncthreads();
    int pref = (w > 0) ? sS[w - 1] : 0;
    if (total) *total = sS[7];
    int r = pref + x - v;
    __syncthreads();
    return r;
}

// ---- gemm phase: g_hw = (preop(in) @ W) * dinv ----
// tile = 128 nodes; 256 threads; thread = 2 nodes x 16 cols (f32x2)
__device__ __forceinline__ void gemm_phase(
    const float* __restrict__ in, const float* __restrict__ W,
    const float* __restrict__ preb, int hasPre, int N,
    float* sIn /*128*65 floats*/, int nb)
{
    int t = threadIdx.x;
    int tiles = (N + 127) / 128;
    for (int tile = blockIdx.x; tile < tiles; tile += nb) {
        __syncthreads();
        // load 128x64 input tile (2048 float4 by 256 threads x8)
#pragma unroll
        for (int r = 0; r < 8; r++) {
            int lin = t + r * 256;
            int n = lin >> 4;
            int c4 = (lin & 15) * 4;
            int i = tile * 128 + n;
            float4 v = make_float4(0.f, 0.f, 0.f, 0.f);
            if (i < N) v = *(const float4*)&in[i * 64 + c4];
            if (hasPre) {
                v.x = fmaxf(v.x + preb[c4 + 0], 0.f);
                v.y = fmaxf(v.y + preb[c4 + 1], 0.f);
                v.z = fmaxf(v.z + preb[c4 + 2], 0.f);
                v.w = fmaxf(v.w + preb[c4 + 3], 0.f);
            }
            float* s = &sIn[n * 65 + c4];
            s[0] = v.x; s[1] = v.y; s[2] = v.z; s[3] = v.w;
        }
        __syncthreads();

        int q  = t & 3;          // col quarter
        int np = t >> 2;         // node pair 0..63
        int na = 2 * np, nb2 = na + 1;

        u64 acc0[8], acc1[8];
#pragma unroll
        for (int j = 0; j < 8; j++) { acc0[j] = 0ull; acc1[j] = 0ull; }

        const float4* __restrict__ Wq = (const float4*)(W + q * 16);
#pragma unroll 8
        for (int k = 0; k < 64; k++) {
            u64 h0 = pack2(sIn[na  * 65 + k]);
            u64 h1 = pack2(sIn[nb2 * 65 + k]);
            const float4* wp = Wq + k * 16;
            F4U2 w0, w1, w2, w3;
            w0.f = __ldg(wp);     w1.f = __ldg(wp + 1);
            w2.f = __ldg(wp + 2); w3.f = __ldg(wp + 3);
            ffma2(acc0[0], h0, w0.u[0]); ffma2(acc0[1], h0, w0.u[1]);
            ffma2(acc0[2], h0, w1.u[0]); ffma2(acc0[3], h0, w1.u[1]);
            ffma2(acc0[4], h0, w2.u[0]); ffma2(acc0[5], h0, w2.u[1]);
            ffma2(acc0[6], h0, w3.u[0]); ffma2(acc0[7], h0, w3.u[1]);
            ffma2(acc1[0], h1, w0.u[0]); ffma2(acc1[1], h1, w0.u[1]);
            ffma2(acc1[2], h1, w1.u[0]); ffma2(acc1[3], h1, w1.u[1]);
            ffma2(acc1[4], h1, w2.u[0]); ffma2(acc1[5], h1, w2.u[1]);
            ffma2(acc1[6], h1, w3.u[0]); ffma2(acc1[7], h1, w3.u[1]);
        }

        int ia = tile * 128 + na;
        int ib = tile * 128 + nb2;
        if (ia < N) {
            float da = g_dinv[ia];
            float* p = &g_hw[ia * 64 + q * 16];
#pragma unroll
            for (int r = 0; r < 4; r++) {
                F4U2 o; o.u[0] = acc0[2*r]; o.u[1] = acc0[2*r+1];
                o.f.x *= da; o.f.y *= da; o.f.z *= da; o.f.w *= da;
                *(float4*)&p[r * 4] = o.f;
            }
        }
        if (ib < N) {
            float db = g_dinv[ib];
            float* p = &g_hw[ib * 64 + q * 16];
#pragma unroll
            for (int r = 0; r < 4; r++) {
                F4U2 o; o.u[0] = acc1[2*r]; o.u[1] = acc1[2*r+1];
                o.f.x *= db; o.f.y *= db; o.f.z *= db; o.f.w *= db;
                *(float4*)&p[r * 4] = o.f;
            }
        }
    }
}

// ---- aggregate phase: agg_i = dinv_i * (hws_i + sum hws[src]) ----
__device__ __forceinline__ void agg_phase(float* __restrict__ agg, int N,
                                          unsigned T, unsigned gid)
{
    for (unsigned u = gid; u < (unsigned)(N * 16); u += T) {
        int i = u >> 4;
        int c4 = (u & 15) * 4;

        float4 acc = *(const float4*)&g_hw[i * 64 + c4];
        int j = g_off[i];
        int end = g_off[i + 1];

        while (j + 8 <= end) {
            int s0 = g_csr[j+0], s1 = g_csr[j+1], s2 = g_csr[j+2], s3 = g_csr[j+3];
            int s4 = g_csr[j+4], s5 = g_csr[j+5], s6 = g_csr[j+6], s7 = g_csr[j+7];
            float4 v0 = __ldcg((const float4*)&g_hw[s0 * 64 + c4]);
            float4 v1 = __ldcg((const float4*)&g_hw[s1 * 64 + c4]);
            float4 v2 = __ldcg((const float4*)&g_hw[s2 * 64 + c4]);
            float4 v3 = __ldcg((const float4*)&g_hw[s3 * 64 + c4]);
            float4 v4 = __ldcg((const float4*)&g_hw[s4 * 64 + c4]);
            float4 v5 = __ldcg((const float4*)&g_hw[s5 * 64 + c4]);
            float4 v6 = __ldcg((const float4*)&g_hw[s6 * 64 + c4]);
            float4 v7 = __ldcg((const float4*)&g_hw[s7 * 64 + c4]);
            acc.x += ((v0.x+v1.x)+(v2.x+v3.x)) + ((v4.x+v5.x)+(v6.x+v7.x));
            acc.y += ((v0.y+v1.y)+(v2.y+v3.y)) + ((v4.y+v5.y)+(v6.y+v7.y));
            acc.z += ((v0.z+v1.z)+(v2.z+v3.z)) + ((v4.z+v5.z)+(v6.z+v7.z));
            acc.w += ((v0.w+v1.w)+(v2.w+v3.w)) + ((v4.w+v5.w)+(v6.w+v7.w));
            j += 8;
        }
        if (j + 4 <= end) {
            int s0 = g_csr[j+0], s1 = g_csr[j+1], s2 = g_csr[j+2], s3 = g_csr[j+3];
            float4 v0 = __ldcg((const float4*)&g_hw[s0 * 64 + c4]);
            float4 v1 = __ldcg((const float4*)&g_hw[s1 * 64 + c4]);
            float4 v2 = __ldcg((const float4*)&g_hw[s2 * 64 + c4]);
            float4 v3 = __ldcg((const float4*)&g_hw[s3 * 64 + c4]);
            acc.x += (v0.x+v1.x)+(v2.x+v3.x);
            acc.y += (v0.y+v1.y)+(v2.y+v3.y);
            acc.z += (v0.z+v1.z)+(v2.z+v3.z);
            acc.w += (v0.w+v1.w)+(v2.w+v3.w);
            j += 4;
        }
        if (j + 2 <= end) {
            int s0 = g_csr[j], s1 = g_csr[j+1];
            float4 v0 = __ldcg((const float4*)&g_hw[s0 * 64 + c4]);
            float4 v1 = __ldcg((const float4*)&g_hw[s1 * 64 + c4]);
            acc.x += v0.x+v1.x; acc.y += v0.y+v1.y;
            acc.z += v0.z+v1.z; acc.w += v0.w+v1.w;
            j += 2;
        }
        if (j < end) {
            float4 v0 = __ldcg((const float4*)&g_hw[g_csr[j] * 64 + c4]);
            acc.x += v0.x; acc.y += v0.y; acc.z += v0.z; acc.w += v0.w;
        }

        float dv = g_dinv[i];
        *(float4*)&agg[i * 64 + c4] =
            make_float4(acc.x * dv, acc.y * dv, acc.z * dv, acc.w * dv);
    }
}

// =================== persistent megakernel ===================
__global__ void __launch_bounds__(256, 4) persistent_k(
    const float* __restrict__ x, const int* __restrict__ src,
    const int* __restrict__ dst,
    const float* __restrict__ W_enc, const float* __restrict__ b_enc,
    const float* __restrict__ conv_W, const float* __restrict__ conv_b,
    const float* __restrict__ Wd1, const float* __restrict__ bd1,
    const float* __restrict__ Wd2, const float* __restrict__ bd2,
    const float* __restrict__ Wi1, const float* __restrict__ bi1,
    const float* __restrict__ Wi2, const float* __restrict__ bi2,
    float* __restrict__ out, int N, int E, int nb)
{
    __shared__ float sBuf[8352];           // 33.4KB union: gemm tile / heads / scan
    int* sS = (int*)&sBuf[8320];           // 32-int scan scratch

    int t = threadIdx.x;
    int bid = blockIdx.x;
    unsigned T = (unsigned)nb * 256u;
    unsigned gid = (unsigned)bid * 256u + (unsigned)t;

    // ---------- P0: encoder + degree histogram ----------
    for (int i = t; i < 320; i += 256) sBuf[i] = W_enc[i];
    if (t < 64) sBuf[320 + t] = b_enc[t];
    __syncthreads();
    for (unsigned u = gid; u < (unsigned)(N * 16); u += T) {
        int i = u >> 4;
        int c = (u & 15) * 4;
        float xv[5];
#pragma unroll
        for (int f = 0; f < 5; f++) xv[f] = x[i * 5 + f];
        float a0 = sBuf[320+c], a1 = sBuf[320+c+1], a2 = sBuf[320+c+2], a3 = sBuf[320+c+3];
#pragma unroll
        for (int f = 0; f < 5; f++) {
            const float* wr = &sBuf[f * 64 + c];
            a0 += xv[f] * wr[0]; a1 += xv[f] * wr[1];
            a2 += xv[f] * wr[2]; a3 += xv[f] * wr[3];
        }
        float4 o;
        o.x = fmaxf(a0, 0.f); o.y = fmaxf(a1, 0.f);
        o.z = fmaxf(a2, 0.f); o.w = fmaxf(a3, 0.f);
        *(float4*)&g_h[i * 64 + c] = o;
    }
    for (unsigned e = gid; e < (unsigned)E; e += T)
        atomicAdd(&g_cnt[dst[e]], 1);
    gsync(0, nb);

    // ---------- P1: per-block chunk sums ----------
    int chunk = (N + nb - 1) / nb;
    int lo = bid * chunk;
    int hi = min(N, lo + chunk);
    {
        int s = 0;
        for (int i = lo + t; i < hi; i += 256) s += g_cnt[i];
        int tot;
        block_excl_scan(s, sS, &tot);
        if (t == 0) g_part[bid] = tot;
    }
    gsync(1, nb);

    // ---------- P2: block 0 scans the nb partials ----------
    if (bid == 0) {
        int per = (nb + 255) / 256;     // <= 8
        int loc[8];
        int s = 0;
#pragma unroll 8
        for (int r = 0; r < per; r++) {
            int idx = t * per + r;
            int v = (idx < nb) ? g_part[idx] : 0;
            loc[r] = s; s += v;
        }
        int tot;
        int excl = block_excl_scan(s, sS, &tot);
#pragma unroll 8
        for (int r = 0; r < per; r++) {
            int idx = t * per + r;
            if (idx < nb) g_part[idx] = excl + loc[r];
        }
        if (t == 0) g_off[N] = tot;
    }
    gsync(2, nb);

    // ---------- P3: local scan -> off/cur/dinv (+ cnt self-clear) ----------
    {
        int base = g_part[bid];
        int cl = hi - lo;
        int per = (cl + 255) / 256;       // <= 8
        int loc[8], cvals[8];
        int s = 0;
#pragma unroll 8
        for (int r = 0; r < per; r++) {
            int i = lo + t * per + r;
            int v = (t * per + r < cl) ? g_cnt[i] : 0;
            cvals[r] = v; loc[r] = s; s += v;
        }
        int excl = block_excl_scan(s, sS, nullptr) + base;
#pragma unroll 8
        for (int r = 0; r < per; r++) {
            int i = lo + t * per + r;
            if (t * per + r < cl) {
                int off = excl + loc[r];
                g_cnt[i] = 0;
                g_off[i] = off;
                g_cur[i] = off;
                g_dinv[i] = rsqrtf(1.0f + (float)cvals[r]);
            }
        }
    }
    gsync(3, nb);

    // ---------- P4: CSR fill + gemm layer0 ----------
    for (unsigned e = gid; e < (unsigned)E; e += T) {
        int s = src[e];
        int c = dst[e];
        int pos = atomicAdd(&g_cur[c], 1);
        g_csr[pos] = s;
    }
    gemm_phase(g_h, conv_W, nullptr, 0, N, sBuf, nb);
    gsync(4, nb);

    // ---------- P5..P9: aggregate / gemm alternation ----------
    agg_phase(g_aggA, N, T, gid);
    gsync(5, nb);
    gemm_phase(g_aggA, conv_W + 4096, conv_b, 1, N, sBuf, nb);
    gsync(6, nb);
    agg_phase(g_aggB, N, T, gid);
    gsync(7, nb);
    gemm_phase(g_aggB, conv_W + 8192, conv_b + 64, 1, N, sBuf, nb);
    gsync(8, nb);
    agg_phase(g_aggA, N, T, gid);
    gsync(9, nb);

    // ---------- P10: heads ----------
    {
        float* sWd1 = &sBuf[0];        // 2048
        float* sWi1 = &sBuf[2048];     // 2048
        float* sWd2 = &sBuf[4096];
        float* sWi2 = &sBuf[4128];
        float* sbd1 = &sBuf[4160];
        float* sbi1 = &sBuf[4192];
        float* scb  = &sBuf[4224];     // 64
        float* sh   = &sBuf[4288];     // 512

        __syncthreads();
        {
            const float4* wd = (const float4*)Wd1;
            const float4* wi = (const float4*)Wi1;
            float4* swd = (float4*)sWd1;
            float4* swi = (float4*)sWi1;
            swd[t] = wd[t]; swd[t + 256] = wd[t + 256];
            swi[t] = wi[t]; swi[t + 256] = wi[t + 256];
        }
        if (t < 32) { sWd2[t] = Wd2[t]; sWi2[t] = Wi2[t]; sbd1[t] = bd1[t]; sbi1[t] = bi1[t]; }
        if (t < 64) scb[t] = conv_b[128 + t];
        __syncthreads();

        int w = t >> 5, lane = t & 31;
        unsigned nwarps = (unsigned)nb * 8u;
        float bd2v = bd2[0], bi2v = bi2[0];
        for (unsigned i = (unsigned)bid * 8u + (unsigned)w; i < (unsigned)N; i += nwarps) {
            float v0 = fmaxf(g_aggA[i * 64 + lane]      + scb[lane],      0.f);
            float v1 = fmaxf(g_aggA[i * 64 + lane + 32] + scb[lane + 32], 0.f);
            sh[w * 64 + lane] = v0;
            sh[w * 64 + lane + 32] = v1;
            __syncwarp();

            float ad = sbd1[lane];
            float ai = sbi1[lane];
#pragma unroll 16
            for (int k = 0; k < 64; k++) {
                float hv = sh[w * 64 + k];
                ad += hv * sWd1[k * 32 + lane];
                ai += hv * sWi1[k * 32 + lane];
            }
            float vd = fmaxf(ad, 0.f) * sWd2[lane];
            float vi = fmaxf(ai, 0.f) * sWi2[lane];
#pragma unroll
            for (int o = 16; o > 0; o >>= 1) {
                vd += __shfl_xor_sync(0xffffffffu, vd, o);
                vi += __shfl_xor_sync(0xffffffffu, vi, o);
            }
            if (lane == 0) {
                out[i]     = vd + bd2v;
                out[N + i] = vi + bi2v;
            }
            __syncwarp();
        }
    }
}

// ---------------- launch ----------------
extern "C" void kernel_launch(void* const* d_in, const int* in_sizes, int n_in,
                              void* d_out, int out_size)
{
    const float* x      = (const float*)d_in[0];
    const int*   ei     = (const int*)d_in[1];     // int32 (JAX x64 off)
    const float* W_enc  = (const float*)d_in[2];
    const float* b_enc  = (const float*)d_in[3];
    const float* conv_W = (const float*)d_in[4];
    const float* conv_b = (const float*)d_in[5];
    const float* W_d1   = (const float*)d_in[6];
    const float* b_d1   = (const float*)d_in[7];
    const float* W_d2   = (const float*)d_in[8];
    const float* b_d2   = (const float*)d_in[9];
    const float* W_i1   = (const float*)d_in[10];
    const float* b_i1   = (const float*)d_in[11];
    const float* W_i2   = (const float*)d_in[12];
    const float* b_i2   = (const float*)d_in[13];
    float* out = (float*)d_out;

    int N = in_sizes[0] / 5;
    int E = in_sizes[1] / 2;
    const int* src = ei;
    const int* dst = ei + E;

    int dev = 0;
    cudaGetDevice(&dev);
    int sms = 148;
    cudaDeviceGetAttribute(&sms, cudaDevAttrMultiProcessorCount, dev);
    int bpm = 0;
    cudaOccupancyMaxActiveBlocksPerMultiprocessor(&bpm, persistent_k, 256, 0);
    if (bpm < 1) bpm = 1;
    if (bpm > 4) bpm = 4;
    int nb = sms * bpm;
    if (nb > 2048) nb = 2048;

    persistent_k<<<nb, 256>>>(x, src, dst, W_enc, b_enc, conv_W, conv_b,
                              W_d1, b_d1, W_d2, b_d2,
                              W_i1, b_i1, W_i2, b_i2,
                              out, N, E, nb);
}

// round 11
// speedup vs baseline: 1.2566x; 1.0768x over previous
#include <cuda_runtime.h>

#define H 64
#define NMAX 50000
#define EMAX 800000

typedef unsigned long long u64;

// ---- static scratch (no allocations allowed) ----
__device__ float g_hw0[NMAX * H];   // hw buffer ping
__device__ float g_hw1[NMAX * H];   // hw buffer pong
__device__ float g_h[NMAX * H];     // encoder output
__device__ float g_dinv[NMAX];
__device__ int   g_cnt[NMAX];       // zero-init; self-cleared each call
__device__ int   g_off[NMAX + 1];
__device__ int   g_cur[NMAX];
__device__ int   g_csr[EMAX];
__device__ int   g_part[2048];

// ---- software grid barrier (self-resetting; zero-init) ----
__device__ volatile unsigned g_arr[16];
__device__ volatile unsigned g_dep[16];

__device__ __forceinline__ void gsync(int p, unsigned nb) {
    __syncthreads();
    if (threadIdx.x == 0) {
        __threadfence();
        atomicAdd((unsigned*)&g_arr[p], 1u);
        while (g_arr[p] < nb) __nanosleep(64);
        __threadfence();
        unsigned d = atomicAdd((unsigned*)&g_dep[p], 1u) + 1;
        if (d == nb) {
            g_arr[p] = 0;
            __threadfence();
            g_dep[p] = 0;
        }
    }
    __syncthreads();
}

// packed f32x2 helpers
__device__ __forceinline__ void ffma2(u64& d, u64 a, u64 b) {
    asm("fma.rn.f32x2 %0, %1, %2, %3;" : "=l"(d) : "l"(a), "l"(b), "l"(d));
}
__device__ __forceinline__ u64 pack2(float v) {
    u64 r; unsigned u = __float_as_uint(v);
    asm("mov.b64 %0, {%1, %1};" : "=l"(r) : "r"(u));
    return r;
}
union F4U2 { float4 f; u64 u[2]; };

// block-wide exclusive scan (256 thr); sS = 32-int scratch
__device__ __forceinline__ int block_excl_scan(int v, int* sS, int* total) {
    int t = threadIdx.x, lane = t & 31, w = t >> 5;
    int x = v;
#pragma unroll
    for (int o = 1; o < 32; o <<= 1) {
        int y = __shfl_up_sync(0xffffffffu, x, o);
        if (lane >= o) x += y;
    }
    if (lane == 31) sS[w] = x;
    __syncthreads();
    if (w == 0) {
        int s = (lane < 8) ? sS[lane] : 0;
#pragma unroll
        for (int o = 1; o < 8; o <<= 1) {
            int y = __shfl_up_sync(0xffffffffu, s, o);
            if (lane >= o) s += y;
        }
        if (lane < 8) sS[lane] = s;
    }
    __syncthreads();
    int pref = (w > 0) ? sS[w - 1] : 0;
    if (total) *total = sS[7];
    int r = pref + x - v;
    __syncthreads();
    return r;
}

// ---- per-node pull aggregate: returns dinv_i*(hws_i + sum hws[src]) for 4 cols
__device__ __forceinline__ float4 agg_node(const float* __restrict__ hwIn,
                                           int i, int c4)
{
    float4 acc = *(const float4*)&hwIn[i * 64 + c4];
    int j = g_off[i];
    int end = g_off[i + 1];

    while (j + 8 <= end) {
        int s0 = g_csr[j+0], s1 = g_csr[j+1], s2 = g_csr[j+2], s3 = g_csr[j+3];
        int s4 = g_csr[j+4], s5 = g_csr[j+5], s6 = g_csr[j+6], s7 = g_csr[j+7];
        float4 v0 = __ldcg((const float4*)&hwIn[s0 * 64 + c4]);
        float4 v1 = __ldcg((const float4*)&hwIn[s1 * 64 + c4]);
        float4 v2 = __ldcg((const float4*)&hwIn[s2 * 64 + c4]);
        float4 v3 = __ldcg((const float4*)&hwIn[s3 * 64 + c4]);
        float4 v4 = __ldcg((const float4*)&hwIn[s4 * 64 + c4]);
        float4 v5 = __ldcg((const float4*)&hwIn[s5 * 64 + c4]);
        float4 v6 = __ldcg((const float4*)&hwIn[s6 * 64 + c4]);
        float4 v7 = __ldcg((const float4*)&hwIn[s7 * 64 + c4]);
        acc.x += ((v0.x+v1.x)+(v2.x+v3.x)) + ((v4.x+v5.x)+(v6.x+v7.x));
        acc.y += ((v0.y+v1.y)+(v2.y+v3.y)) + ((v4.y+v5.y)+(v6.y+v7.y));
        acc.z += ((v0.z+v1.z)+(v2.z+v3.z)) + ((v4.z+v5.z)+(v6.z+v7.z));
        acc.w += ((v0.w+v1.w)+(v2.w+v3.w)) + ((v4.w+v5.w)+(v6.w+v7.w));
        j += 8;
    }
    if (j + 4 <= end) {
        int s0 = g_csr[j+0], s1 = g_csr[j+1], s2 = g_csr[j+2], s3 = g_csr[j+3];
        float4 v0 = __ldcg((const float4*)&hwIn[s0 * 64 + c4]);
        float4 v1 = __ldcg((const float4*)&hwIn[s1 * 64 + c4]);
        float4 v2 = __ldcg((const float4*)&hwIn[s2 * 64 + c4]);
        float4 v3 = __ldcg((const float4*)&hwIn[s3 * 64 + c4]);
        acc.x += (v0.x+v1.x)+(v2.x+v3.x);
        acc.y += (v0.y+v1.y)+(v2.y+v3.y);
        acc.z += (v0.z+v1.z)+(v2.z+v3.z);
        acc.w += (v0.w+v1.w)+(v2.w+v3.w);
        j += 4;
    }
    if (j + 2 <= end) {
        int s0 = g_csr[j], s1 = g_csr[j+1];
        float4 v0 = __ldcg((const float4*)&hwIn[s0 * 64 + c4]);
        float4 v1 = __ldcg((const float4*)&hwIn[s1 * 64 + c4]);
        acc.x += v0.x+v1.x; acc.y += v0.y+v1.y;
        acc.z += v0.z+v1.z; acc.w += v0.w+v1.w;
        j += 2;
    }
    if (j < end) {
        float4 v0 = __ldcg((const float4*)&hwIn[g_csr[j] * 64 + c4]);
        acc.x += v0.x; acc.y += v0.y; acc.z += v0.z; acc.w += v0.w;
    }

    float dv = g_dinv[i];
    return make_float4(acc.x * dv, acc.y * dv, acc.z * dv, acc.w * dv);
}

// ---- gemm from smem tile -> hwOut (2 nodes x 16 cols per thread, f32x2) ----
__device__ __forceinline__ void gemm_from_smem(
    const float* __restrict__ W, float* __restrict__ hwOut,
    int tileBase, int N, const float* sIn)
{
    int t = threadIdx.x;
    int q  = t & 3;
    int np = t >> 2;
    int na = 2 * np, nb2 = na + 1;

    u64 acc0[8], acc1[8];
#pragma unroll
    for (int j = 0; j < 8; j++) { acc0[j] = 0ull; acc1[j] = 0ull; }

    const float4* __restrict__ Wq = (const float4*)(W + q * 16);
#pragma unroll 8
    for (int k = 0; k < 64; k++) {
        u64 h0 = pack2(sIn[na  * 65 + k]);
        u64 h1 = pack2(sIn[nb2 * 65 + k]);
        const float4* wp = Wq + k * 16;
        F4U2 w0, w1, w2, w3;
        w0.f = __ldg(wp);     w1.f = __ldg(wp + 1);
        w2.f = __ldg(wp + 2); w3.f = __ldg(wp + 3);
        ffma2(acc0[0], h0, w0.u[0]); ffma2(acc0[1], h0, w0.u[1]);
        ffma2(acc0[2], h0, w1.u[0]); ffma2(acc0[3], h0, w1.u[1]);
        ffma2(acc0[4], h0, w2.u[0]); ffma2(acc0[5], h0, w2.u[1]);
        ffma2(acc0[6], h0, w3.u[0]); ffma2(acc0[7], h0, w3.u[1]);
        ffma2(acc1[0], h1, w0.u[0]); ffma2(acc1[1], h1, w0.u[1]);
        ffma2(acc1[2], h1, w1.u[0]); ffma2(acc1[3], h1, w1.u[1]);
        ffma2(acc1[4], h1, w2.u[0]); ffma2(acc1[5], h1, w2.u[1]);
        ffma2(acc1[6], h1, w3.u[0]); ffma2(acc1[7], h1, w3.u[1]);
    }

    int ia = tileBase + na;
    int ib = tileBase + nb2;
    if (ia < N) {
        float da = g_dinv[ia];
        float* p = &hwOut[ia * 64 + q * 16];
#pragma unroll
        for (int r = 0; r < 4; r++) {
            F4U2 o; o.u[0] = acc0[2*r]; o.u[1] = acc0[2*r+1];
            o.f.x *= da; o.f.y *= da; o.f.z *= da; o.f.w *= da;
            *(float4*)&p[r * 4] = o.f;
        }
    }
    if (ib < N) {
        float db = g_dinv[ib];
        float* p = &hwOut[ib * 64 + q * 16];
#pragma unroll
        for (int r = 0; r < 4; r++) {
            F4U2 o; o.u[0] = acc1[2*r]; o.u[1] = acc1[2*r+1];
            o.f.x *= db; o.f.y *= db; o.f.z *= db; o.f.w *= db;
            *(float4*)&p[r * 4] = o.f;
        }
    }
}

// ---- gemm layer0: reads g_h (already relu'd), tiles of 128 nodes ----
__device__ __forceinline__ void gemm0_phase(
    const float* __restrict__ W, float* __restrict__ hwOut, int N,
    float* sIn, int nb)
{
    int t = threadIdx.x;
    int tiles = (N + 127) / 128;
    for (int tile = blockIdx.x; tile < tiles; tile += nb) {
        __syncthreads();
#pragma unroll
        for (int r = 0; r < 8; r++) {
            int lin = t + r * 256;
            int n = lin >> 4;
            int c4 = (lin & 15) * 4;
            int i = tile * 128 + n;
            float4 v = make_float4(0.f, 0.f, 0.f, 0.f);
            if (i < N) v = *(const float4*)&g_h[i * 64 + c4];
            float* s = &sIn[n * 65 + c4];
            s[0] = v.x; s[1] = v.y; s[2] = v.z; s[3] = v.w;
        }
        __syncthreads();
        gemm_from_smem(W, hwOut, tile * 128, N, sIn);
    }
}

// ---- fused: aggregate(hwIn) -> relu(+b) -> smem -> gemm -> hwOut ----
__device__ __forceinline__ void fused_agg_gemm_phase(
    const float* __restrict__ hwIn, float* __restrict__ hwOut,
    const float* __restrict__ W, const float* __restrict__ preb,
    int N, float* sIn, int nb)
{
    int t = threadIdx.x;
    int c4 = (t & 15) * 4;
    int nsub = t >> 4;                 // node-slot within 16-node pass
    int tiles = (N + 127) / 128;
    for (int tile = blockIdx.x; tile < tiles; tile += nb) {
        __syncthreads();
#pragma unroll 1
        for (int p = 0; p < 8; p++) {
            int n = p * 16 + nsub;
            int i = tile * 128 + n;
            float4 a = make_float4(0.f, 0.f, 0.f, 0.f);
            if (i < N) {
                a = agg_node(hwIn, i, c4);
                a.x = fmaxf(a.x + preb[c4 + 0], 0.f);
                a.y = fmaxf(a.y + preb[c4 + 1], 0.f);
                a.z = fmaxf(a.z + preb[c4 + 2], 0.f);
                a.w = fmaxf(a.w + preb[c4 + 3], 0.f);
            }
            float* s = &sIn[n * 65 + c4];
            s[0] = a.x; s[1] = a.y; s[2] = a.z; s[3] = a.w;
        }
        __syncthreads();
        gemm_from_smem(W, hwOut, tile * 128, N, sIn);
    }
}

// =================== persistent megakernel ===================
__global__ void __launch_bounds__(256, 4) persistent_k(
    const float* __restrict__ x, const int* __restrict__ src,
    const int* __restrict__ dst,
    const float* __restrict__ W_enc, const float* __restrict__ b_enc,
    const float* __restrict__ conv_W, const float* __restrict__ conv_b,
    const float* __restrict__ Wd1, const float* __restrict__ bd1,
    const float* __restrict__ Wd2, const float* __restrict__ bd2,
    const float* __restrict__ Wi1, const float* __restrict__ bi1,
    const float* __restrict__ Wi2, const float* __restrict__ bi2,
    float* __restrict__ out, int N, int E, int nb)
{
    __shared__ float sBuf[8352];           // union: gemm tile / heads / scan
    int* sS = (int*)&sBuf[8320];

    int t = threadIdx.x;
    int bid = blockIdx.x;
    unsigned T = (unsigned)nb * 256u;
    unsigned gid = (unsigned)bid * 256u + (unsigned)t;

    // ---------- P0: encoder + degree histogram ----------
    for (int i = t; i < 320; i += 256) sBuf[i] = W_enc[i];
    if (t < 64) sBuf[320 + t] = b_enc[t];
    __syncthreads();
    for (unsigned u = gid; u < (unsigned)(N * 16); u += T) {
        int i = u >> 4;
        int c = (u & 15) * 4;
        float xv[5];
#pragma unroll
        for (int f = 0; f < 5; f++) xv[f] = x[i * 5 + f];
        float a0 = sBuf[320+c], a1 = sBuf[320+c+1], a2 = sBuf[320+c+2], a3 = sBuf[320+c+3];
#pragma unroll
        for (int f = 0; f < 5; f++) {
            const float* wr = &sBuf[f * 64 + c];
            a0 += xv[f] * wr[0]; a1 += xv[f] * wr[1];
            a2 += xv[f] * wr[2]; a3 += xv[f] * wr[3];
        }
        float4 o;
        o.x = fmaxf(a0, 0.f); o.y = fmaxf(a1, 0.f);
        o.z = fmaxf(a2, 0.f); o.w = fmaxf(a3, 0.f);
        *(float4*)&g_h[i * 64 + c] = o;
    }
    for (unsigned e = gid; e < (unsigned)E; e += T)
        atomicAdd(&g_cnt[dst[e]], 1);
    gsync(0, nb);

    // ---------- P1: per-block chunk sums ----------
    int chunk = (N + nb - 1) / nb;
    int lo = bid * chunk;
    int hi = min(N, lo + chunk);
    {
        int s = 0;
        for (int i = lo + t; i < hi; i += 256) s += g_cnt[i];
        int tot;
        block_excl_scan(s, sS, &tot);
        if (t == 0) g_part[bid] = tot;
    }
    gsync(1, nb);

    // ---------- P2: block 0 scans the nb partials ----------
    if (bid == 0) {
        int per = (nb + 255) / 256;
        int loc[8];
        int s = 0;
#pragma unroll 8
        for (int r = 0; r < per; r++) {
            int idx = t * per + r;
            int v = (idx < nb) ? g_part[idx] : 0;
            loc[r] = s; s += v;
        }
        int tot;
        int excl = block_excl_scan(s, sS, &tot);
#pragma unroll 8
        for (int r = 0; r < per; r++) {
            int idx = t * per + r;
            if (idx < nb) g_part[idx] = excl + loc[r];
        }
        if (t == 0) g_off[N] = tot;
    }
    gsync(2, nb);

    // ---------- P3: local scan -> off/cur/dinv (+ cnt self-clear) ----------
    {
        int base = g_part[bid];
        int cl = hi - lo;
        int per = (cl + 255) / 256;
        int loc[8], cvals[8];
        int s = 0;
#pragma unroll 8
        for (int r = 0; r < per; r++) {
            int i = lo + t * per + r;
            int v = (t * per + r < cl) ? g_cnt[i] : 0;
            cvals[r] = v; loc[r] = s; s += v;
        }
        int excl = block_excl_scan(s, sS, nullptr) + base;
#pragma unroll 8
        for (int r = 0; r < per; r++) {
            int i = lo + t * per + r;
            if (t * per + r < cl) {
                int off = excl + loc[r];
                g_cnt[i] = 0;
                g_off[i] = off;
                g_cur[i] = off;
                g_dinv[i] = rsqrtf(1.0f + (float)cvals[r]);
            }
        }
    }
    gsync(3, nb);

    // ---------- P4: CSR fill + gemm layer0 (g_h -> hw0) ----------
    for (unsigned e = gid; e < (unsigned)E; e += T) {
        int s = src[e];
        int c = dst[e];
        int pos = atomicAdd(&g_cur[c], 1);
        g_csr[pos] = s;
    }
    gemm0_phase(conv_W, g_hw0, N, sBuf, nb);
    gsync(4, nb);

    // ---------- P5: agg(hw0)+gemm1 -> hw1 ----------
    fused_agg_gemm_phase(g_hw0, g_hw1, conv_W + 4096, conv_b, N, sBuf, nb);
    gsync(5, nb);

    // ---------- P6: agg(hw1)+gemm2 -> hw0 ----------
    fused_agg_gemm_phase(g_hw1, g_hw0, conv_W + 8192, conv_b + 64, N, sBuf, nb);
    gsync(6, nb);

    // ---------- P7: agg(hw0) + heads (per-warp, no global agg buffer) -------
    {
        float* sWd1 = &sBuf[0];        // 2048
        float* sWi1 = &sBuf[2048];     // 2048
        float* sWd2 = &sBuf[4096];
        float* sWi2 = &sBuf[4128];
        float* sbd1 = &sBuf[4160];
        float* sbi1 = &sBuf[4192];
        float* scb  = &sBuf[4224];     // 64
        float* sh   = &sBuf[4288];     // 8 warps * 2 nodes * 64 = 1024

        {
            const float4* wd = (const float4*)Wd1;
            const float4* wi = (const float4*)Wi1;
            float4* swd = (float4*)sWd1;
            float4* swi = (float4*)sWi1;
            swd[t] = wd[t]; swd[t + 256] = wd[t + 256];
            swi[t] = wi[t]; swi[t + 256] = wi[t + 256];
        }
        if (t < 32) { sWd2[t] = Wd2[t]; sWi2[t] = Wi2[t]; sbd1[t] = bd1[t]; sbi1[t] = bi1[t]; }
        if (t < 64) scb[t] = conv_b[128 + t];
        __syncthreads();

        int w = t >> 5, lane = t & 31;
        int nw = (t >> 4) & 1;           // node slot within warp
        int c4 = (t & 15) * 4;
        float bd2v = bd2[0], bi2v = bi2[0];
        float* shw = &sh[w * 128];

        for (int base = bid * 16; base < N; base += nb * 16) {
            int i = base + (t >> 4);     // base + 2w + nw
            float4 a = make_float4(0.f, 0.f, 0.f, 0.f);
            if (i < N) {
                a = agg_node(g_hw0, i, c4);
                a.x = fmaxf(a.x + scb[c4 + 0], 0.f);
                a.y = fmaxf(a.y + scb[c4 + 1], 0.f);
                a.z = fmaxf(a.z + scb[c4 + 2], 0.f);
                a.w = fmaxf(a.w + scb[c4 + 3], 0.f);
            }
            float* s = &shw[nw * 64 + c4];
            s[0] = a.x; s[1] = a.y; s[2] = a.z; s[3] = a.w;
            __syncwarp();

            float ad0 = sbd1[lane], ai0 = sbi1[lane];
            float ad1 = sbd1[lane], ai1 = sbi1[lane];
#pragma unroll 16
            for (int k = 0; k < 64; k++) {
                float h0 = shw[k];
                float h1 = shw[64 + k];
                float wd = sWd1[k * 32 + lane];
                float wi = sWi1[k * 32 + lane];
                ad0 += h0 * wd; ai0 += h0 * wi;
                ad1 += h1 * wd; ai1 += h1 * wi;
            }
            float vd0 = fmaxf(ad0, 0.f) * sWd2[lane];
            float vi0 = fmaxf(ai0, 0.f) * sWi2[lane];
            float vd1 = fmaxf(ad1, 0.f) * sWd2[lane];
            float vi1 = fmaxf(ai1, 0.f) * sWi2[lane];
#pragma unroll
            for (int o = 16; o > 0; o >>= 1) {
                vd0 += __shfl_xor_sync(0xffffffffu, vd0, o);
                vi0 += __shfl_xor_sync(0xffffffffu, vi0, o);
                vd1 += __shfl_xor_sync(0xffffffffu, vd1, o);
                vi1 += __shfl_xor_sync(0xffffffffu, vi1, o);
            }
            int i0 = base + 2 * w;
            if (lane == 0 && i0 < N) {
                out[i0]     = vd0 + bd2v;
                out[N + i0] = vi0 + bi2v;
                int i1 = i0 + 1;
                if (i1 < N) {
                    out[i1]     = vd1 + bd2v;
                    out[N + i1] = vi1 + bi2v;
                }
            }
            __syncwarp();
        }
    }
}

// ---------------- launch ----------------
extern "C" void kernel_launch(void* const* d_in, const int* in_sizes, int n_in,
                              void* d_out, int out_size)
{
    const float* x      = (const float*)d_in[0];
    const int*   ei     = (const int*)d_in[1];     // int32 (JAX x64 off)
    const float* W_enc  = (const float*)d_in[2];
    const float* b_enc  = (const float*)d_in[3];
    const float* conv_W = (const float*)d_in[4];
    const float* conv_b = (const float*)d_in[5];
    const float* W_d1   = (const float*)d_in[6];
    const float* b_d1   = (const float*)d_in[7];
    const float* W_d2   = (const float*)d_in[8];
    const float* b_d2   = (const float*)d_in[9];
    const float* W_i1   = (const float*)d_in[10];
    const float* b_i1   = (const float*)d_in[11];
    const float* W_i2   = (const float*)d_in[12];
    const float* b_i2   = (const float*)d_in[13];
    float* out = (float*)d_out;

    int N = in_sizes[0] / 5;
    int E = in_sizes[1] / 2;
    const int* src = ei;
    const int* dst = ei + E;

    int dev = 0;
    cudaGetDevice(&dev);
    int sms = 148;
    cudaDeviceGetAttribute(&sms, cudaDevAttrMultiProcessorCount, dev);
    int bpm = 0;
    cudaOccupancyMaxActiveBlocksPerMultiprocessor(&bpm, persistent_k, 256, 0);
    if (bpm < 1) bpm = 1;
    if (bpm > 4) bpm = 4;
    int nb = sms * bpm;
    if (nb > 2048) nb = 2048;

    persistent_k<<<nb, 256>>>(x, src, dst, W_enc, b_enc, conv_W, conv_b,
                              W_d1, b_d1, W_d2, b_d2,
                              W_i1, b_i1, W_i2, b_i2,
                              out, N, E, nb);
}

// round 12
// speedup vs baseline: 1.5855x; 1.2617x over previous
#include <cuda_runtime.h>

#define H 64
#define NMAX 50000
#define EMAX 800000
#define MAXTILE 96

typedef unsigned long long u64;

// ---- static scratch (no allocations allowed) ----
__device__ float g_hw0[NMAX * H];   // hw buffer ping
__device__ float g_hw1[NMAX * H];   // hw buffer pong
__device__ float g_h[NMAX * H];     // encoder output
__device__ float g_dinv[NMAX];
__device__ int   g_cnt[NMAX];       // zero-init; self-cleared each call
__device__ int   g_off[NMAX + 1];
__device__ int   g_cur[NMAX];
__device__ int   g_csr[EMAX];
__device__ int   g_part[2048];

// ---- software grid barrier (self-resetting; zero-init) ----
__device__ volatile unsigned g_arr[16];
__device__ volatile unsigned g_dep[16];

__device__ __forceinline__ void gsync(int p, unsigned nb) {
    __syncthreads();
    if (threadIdx.x == 0) {
        __threadfence();
        atomicAdd((unsigned*)&g_arr[p], 1u);
        while (g_arr[p] < nb) __nanosleep(64);
        __threadfence();
        unsigned d = atomicAdd((unsigned*)&g_dep[p], 1u) + 1;
        if (d == nb) {
            g_arr[p] = 0;
            __threadfence();
            g_dep[p] = 0;
        }
    }
    __syncthreads();
}

// packed f32x2 helpers
__device__ __forceinline__ void ffma2(u64& d, u64 a, u64 b) {
    asm("fma.rn.f32x2 %0, %1, %2, %3;" : "=l"(d) : "l"(a), "l"(b), "l"(d));
}
__device__ __forceinline__ u64 pack2(float v) {
    u64 r; unsigned u = __float_as_uint(v);
    asm("mov.b64 %0, {%1, %1};" : "=l"(r) : "r"(u));
    return r;
}
union F4U2 { float4 f; u64 u[2]; };

// block-wide exclusive scan (256 thr); sS = 32-int scratch
__device__ __forceinline__ int block_excl_scan(int v, int* sS, int* total) {
    int t = threadIdx.x, lane = t & 31, w = t >> 5;
    int x = v;
#pragma unroll
    for (int o = 1; o < 32; o <<= 1) {
        int y = __shfl_up_sync(0xffffffffu, x, o);
        if (lane >= o) x += y;
    }
    if (lane == 31) sS[w] = x;
    __syncthreads();
    if (w == 0) {
        int s = (lane < 8) ? sS[lane] : 0;
#pragma unroll
        for (int o = 1; o < 8; o <<= 1) {
            int y = __shfl_up_sync(0xffffffffu, s, o);
            if (lane >= o) s += y;
        }
        if (lane < 8) sS[lane] = s;
    }
    __syncthreads();
    int pref = (w > 0) ? sS[w - 1] : 0;
    if (total) *total = sS[7];
    int r = pref + x - v;
    __syncthreads();
    return r;
}

// ---- per-node pull aggregate ----
__device__ __forceinline__ float4 agg_node(const float* __restrict__ hwIn,
                                           int i, int c4)
{
    float4 acc = *(const float4*)&hwIn[i * 64 + c4];
    int j = g_off[i];
    int end = g_off[i + 1];

    while (j + 8 <= end) {
        int s0 = g_csr[j+0], s1 = g_csr[j+1], s2 = g_csr[j+2], s3 = g_csr[j+3];
        int s4 = g_csr[j+4], s5 = g_csr[j+5], s6 = g_csr[j+6], s7 = g_csr[j+7];
        float4 v0 = __ldcg((const float4*)&hwIn[s0 * 64 + c4]);
        float4 v1 = __ldcg((const float4*)&hwIn[s1 * 64 + c4]);
        float4 v2 = __ldcg((const float4*)&hwIn[s2 * 64 + c4]);
        float4 v3 = __ldcg((const float4*)&hwIn[s3 * 64 + c4]);
        float4 v4 = __ldcg((const float4*)&hwIn[s4 * 64 + c4]);
        float4 v5 = __ldcg((const float4*)&hwIn[s5 * 64 + c4]);
        float4 v6 = __ldcg((const float4*)&hwIn[s6 * 64 + c4]);
        float4 v7 = __ldcg((const float4*)&hwIn[s7 * 64 + c4]);
        acc.x += ((v0.x+v1.x)+(v2.x+v3.x)) + ((v4.x+v5.x)+(v6.x+v7.x));
        acc.y += ((v0.y+v1.y)+(v2.y+v3.y)) + ((v4.y+v5.y)+(v6.y+v7.y));
        acc.z += ((v0.z+v1.z)+(v2.z+v3.z)) + ((v4.z+v5.z)+(v6.z+v7.z));
        acc.w += ((v0.w+v1.w)+(v2.w+v3.w)) + ((v4.w+v5.w)+(v6.w+v7.w));
        j += 8;
    }
    if (j + 4 <= end) {
        int s0 = g_csr[j+0], s1 = g_csr[j+1], s2 = g_csr[j+2], s3 = g_csr[j+3];
        float4 v0 = __ldcg((const float4*)&hwIn[s0 * 64 + c4]);
        float4 v1 = __ldcg((const float4*)&hwIn[s1 * 64 + c4]);
        float4 v2 = __ldcg((const float4*)&hwIn[s2 * 64 + c4]);
        float4 v3 = __ldcg((const float4*)&hwIn[s3 * 64 + c4]);
        acc.x += (v0.x+v1.x)+(v2.x+v3.x);
        acc.y += (v0.y+v1.y)+(v2.y+v3.y);
        acc.z += (v0.z+v1.z)+(v2.z+v3.z);
        acc.w += (v0.w+v1.w)+(v2.w+v3.w);
        j += 4;
    }
    if (j + 2 <= end) {
        int s0 = g_csr[j], s1 = g_csr[j+1];
        float4 v0 = __ldcg((const float4*)&hwIn[s0 * 64 + c4]);
        float4 v1 = __ldcg((const float4*)&hwIn[s1 * 64 + c4]);
        acc.x += v0.x+v1.x; acc.y += v0.y+v1.y;
        acc.z += v0.z+v1.z; acc.w += v0.w+v1.w;
        j += 2;
    }
    if (j < end) {
        float4 v0 = __ldcg((const float4*)&hwIn[g_csr[j] * 64 + c4]);
        acc.x += v0.x; acc.y += v0.y; acc.z += v0.z; acc.w += v0.w;
    }

    float dv = g_dinv[i];
    return make_float4(acc.x * dv, acc.y * dv, acc.z * dv, acc.w * dv);
}

// ---- gemm from smem tile -> hwOut (2 nodes x 16 cols / thread, f32x2) ----
__device__ __forceinline__ void gemm_from_smem(
    const float* __restrict__ W, float* __restrict__ hwOut,
    int lo, int tileN, int N, const float* sIn)
{
    int t = threadIdx.x;
    int q  = t & 3;
    int np = t >> 2;
    int na = 2 * np, nb2 = na + 1;
    if (na >= tileN) return;          // tileN even -> nb2 < tileN too

    u64 acc0[8], acc1[8];
#pragma unroll
    for (int j = 0; j < 8; j++) { acc0[j] = 0ull; acc1[j] = 0ull; }

    const float4* __restrict__ Wq = (const float4*)(W + q * 16);
#pragma unroll 8
    for (int k = 0; k < 64; k++) {
        u64 h0 = pack2(sIn[na  * 65 + k]);
        u64 h1 = pack2(sIn[nb2 * 65 + k]);
        const float4* wp = Wq + k * 16;
        F4U2 w0, w1, w2, w3;
        w0.f = __ldg(wp);     w1.f = __ldg(wp + 1);
        w2.f = __ldg(wp + 2); w3.f = __ldg(wp + 3);
        ffma2(acc0[0], h0, w0.u[0]); ffma2(acc0[1], h0, w0.u[1]);
        ffma2(acc0[2], h0, w1.u[0]); ffma2(acc0[3], h0, w1.u[1]);
        ffma2(acc0[4], h0, w2.u[0]); ffma2(acc0[5], h0, w2.u[1]);
        ffma2(acc0[6], h0, w3.u[0]); ffma2(acc0[7], h0, w3.u[1]);
        ffma2(acc1[0], h1, w0.u[0]); ffma2(acc1[1], h1, w0.u[1]);
        ffma2(acc1[2], h1, w1.u[0]); ffma2(acc1[3], h1, w1.u[1]);
        ffma2(acc1[4], h1, w2.u[0]); ffma2(acc1[5], h1, w2.u[1]);
        ffma2(acc1[6], h1, w3.u[0]); ffma2(acc1[7], h1, w3.u[1]);
    }

    int ia = lo + na;
    int ib = lo + nb2;
    if (ia < N) {
        float da = g_dinv[ia];
        float* p = &hwOut[ia * 64 + q * 16];
#pragma unroll
        for (int r = 0; r < 4; r++) {
            F4U2 o; o.u[0] = acc0[2*r]; o.u[1] = acc0[2*r+1];
            o.f.x *= da; o.f.y *= da; o.f.z *= da; o.f.w *= da;
            *(float4*)&p[r * 4] = o.f;
        }
    }
    if (ib < N) {
        float db = g_dinv[ib];
        float* p = &hwOut[ib * 64 + q * 16];
#pragma unroll
        for (int r = 0; r < 4; r++) {
            F4U2 o; o.u[0] = acc1[2*r]; o.u[1] = acc1[2*r+1];
            o.f.x *= db; o.f.y *= db; o.f.z *= db; o.f.w *= db;
            *(float4*)&p[r * 4] = o.f;
        }
    }
}

// =================== persistent megakernel ===================
__global__ void __launch_bounds__(256, 4) persistent_k(
    const float* __restrict__ x, const int* __restrict__ src,
    const int* __restrict__ dst,
    const float* __restrict__ W_enc, const float* __restrict__ b_enc,
    const float* __restrict__ conv_W, const float* __restrict__ conv_b,
    const float* __restrict__ Wd1, const float* __restrict__ bd1,
    const float* __restrict__ Wd2, const float* __restrict__ bd2,
    const float* __restrict__ Wi1, const float* __restrict__ bi1,
    const float* __restrict__ Wi2, const float* __restrict__ bi2,
    float* __restrict__ out, int N, int E, int nb, int tileN)
{
    __shared__ float sBuf[MAXTILE * 65 + 32];   // 25KB: gemm tile / heads / scan
    int* sS = (int*)&sBuf[MAXTILE * 65];

    int t = threadIdx.x;
    int bid = blockIdx.x;
    unsigned T = (unsigned)nb * 256u;
    unsigned gid = (unsigned)bid * 256u + (unsigned)t;

    // ---------- P0: encoder + degree histogram ----------
    for (int i = t; i < 320; i += 256) sBuf[i] = W_enc[i];
    if (t < 64) sBuf[320 + t] = b_enc[t];
    __syncthreads();
    for (unsigned u = gid; u < (unsigned)(N * 16); u += T) {
        int i = u >> 4;
        int c = (u & 15) * 4;
        float xv[5];
#pragma unroll
        for (int f = 0; f < 5; f++) xv[f] = x[i * 5 + f];
        float a0 = sBuf[320+c], a1 = sBuf[320+c+1], a2 = sBuf[320+c+2], a3 = sBuf[320+c+3];
#pragma unroll
        for (int f = 0; f < 5; f++) {
            const float* wr = &sBuf[f * 64 + c];
            a0 += xv[f] * wr[0]; a1 += xv[f] * wr[1];
            a2 += xv[f] * wr[2]; a3 += xv[f] * wr[3];
        }
        float4 o;
        o.x = fmaxf(a0, 0.f); o.y = fmaxf(a1, 0.f);
        o.z = fmaxf(a2, 0.f); o.w = fmaxf(a3, 0.f);
        *(float4*)&g_h[i * 64 + c] = o;
    }
    for (unsigned e = gid; e < (unsigned)E; e += T)
        atomicAdd(&g_cnt[dst[e]], 1);
    gsync(0, nb);

    // ---------- P1: per-block chunk sums ----------
    int chunk = (N + nb - 1) / nb;
    int slo = bid * chunk;
    int shi = min(N, slo + chunk);
    {
        int s = 0;
        for (int i = slo + t; i < shi; i += 256) s += g_cnt[i];
        int tot;
        block_excl_scan(s, sS, &tot);
        if (t == 0) g_part[bid] = tot;
    }
    gsync(1, nb);

    // ---------- P2: block 0 scans the nb partials ----------
    if (bid == 0) {
        int per = (nb + 255) / 256;
        int loc[8];
        int s = 0;
#pragma unroll 8
        for (int r = 0; r < per; r++) {
            int idx = t * per + r;
            int v = (idx < nb) ? g_part[idx] : 0;
            loc[r] = s; s += v;
        }
        int tot;
        int excl = block_excl_scan(s, sS, &tot);
#pragma unroll 8
        for (int r = 0; r < per; r++) {
            int idx = t * per + r;
            if (idx < nb) g_part[idx] = excl + loc[r];
        }
        if (t == 0) g_off[N] = tot;
    }
    gsync(2, nb);

    // ---------- P3: local scan -> off/cur/dinv (+ cnt self-clear) ----------
    {
        int base = g_part[bid];
        int cl = shi - slo;
        int per = (cl + 255) / 256;
        int loc[8], cvals[8];
        int s = 0;
#pragma unroll 8
        for (int r = 0; r < per; r++) {
            int i = slo + t * per + r;
            int v = (t * per + r < cl) ? g_cnt[i] : 0;
            cvals[r] = v; loc[r] = s; s += v;
        }
        int excl = block_excl_scan(s, sS, nullptr) + base;
#pragma unroll 8
        for (int r = 0; r < per; r++) {
            int i = slo + t * per + r;
            if (t * per + r < cl) {
                int off = excl + loc[r];
                g_cnt[i] = 0;
                g_off[i] = off;
                g_cur[i] = off;
                g_dinv[i] = rsqrtf(1.0f + (float)cvals[r]);
            }
        }
    }
    gsync(3, nb);

    // ---------- P4: CSR fill + gemm layer0 (g_h -> hw0), one tile/block -----
    for (unsigned e = gid; e < (unsigned)E; e += T) {
        int s = src[e];
        int c = dst[e];
        int pos = atomicAdd(&g_cur[c], 1);
        g_csr[pos] = s;
    }
    for (int tile = bid; tile * tileN < N; tile += nb) {
        int lo = tile * tileN;
        __syncthreads();
        for (int s = t; s < tileN * 16; s += 256) {
            int n = s >> 4;
            int c4 = (s & 15) * 4;
            int i = lo + n;
            float4 v = make_float4(0.f, 0.f, 0.f, 0.f);
            if (i < N) v = *(const float4*)&g_h[i * 64 + c4];
            float* sp = &sBuf[n * 65 + c4];
            sp[0] = v.x; sp[1] = v.y; sp[2] = v.z; sp[3] = v.w;
        }
        __syncthreads();
        gemm_from_smem(conv_W, g_hw0, lo, tileN, N, sBuf);
    }
    gsync(4, nb);

    // ---------- P5: agg(hw0)+gemm1 -> hw1, one tile/block ----------
    for (int tile = bid; tile * tileN < N; tile += nb) {
        int lo = tile * tileN;
        __syncthreads();
        for (int s = t; s < tileN * 16; s += 256) {
            int n = s >> 4;
            int c4 = (s & 15) * 4;
            int i = lo + n;
            float4 a = make_float4(0.f, 0.f, 0.f, 0.f);
            if (i < N) {
                a = agg_node(g_hw0, i, c4);
                a.x = fmaxf(a.x + conv_b[c4 + 0], 0.f);
                a.y = fmaxf(a.y + conv_b[c4 + 1], 0.f);
                a.z = fmaxf(a.z + conv_b[c4 + 2], 0.f);
                a.w = fmaxf(a.w + conv_b[c4 + 3], 0.f);
            }
            float* sp = &sBuf[n * 65 + c4];
            sp[0] = a.x; sp[1] = a.y; sp[2] = a.z; sp[3] = a.w;
        }
        __syncthreads();
        gemm_from_smem(conv_W + 4096, g_hw1, lo, tileN, N, sBuf);
    }
    gsync(5, nb);

    // ---------- P6: agg(hw1)+gemm2 -> hw0, one tile/block ----------
    for (int tile = bid; tile * tileN < N; tile += nb) {
        int lo = tile * tileN;
        __syncthreads();
        for (int s = t; s < tileN * 16; s += 256) {
            int n = s >> 4;
            int c4 = (s & 15) * 4;
            int i = lo + n;
            float4 a = make_float4(0.f, 0.f, 0.f, 0.f);
            if (i < N) {
                a = agg_node(g_hw1, i, c4);
                a.x = fmaxf(a.x + conv_b[64 + c4 + 0], 0.f);
                a.y = fmaxf(a.y + conv_b[64 + c4 + 1], 0.f);
                a.z = fmaxf(a.z + conv_b[64 + c4 + 2], 0.f);
                a.w = fmaxf(a.w + conv_b[64 + c4 + 3], 0.f);
            }
            float* sp = &sBuf[n * 65 + c4];
            sp[0] = a.x; sp[1] = a.y; sp[2] = a.z; sp[3] = a.w;
        }
        __syncthreads();
        gemm_from_smem(conv_W + 8192, g_hw0, lo, tileN, N, sBuf);
    }
    gsync(6, nb);

    // ---------- P7: agg(hw0) + heads, contiguous chunk per block ----------
    {
        float* sWd1 = &sBuf[0];        // 2048
        float* sWi1 = &sBuf[2048];     // 2048
        float* sWd2 = &sBuf[4096];
        float* sWi2 = &sBuf[4128];
        float* sbd1 = &sBuf[4160];
        float* sbi1 = &sBuf[4192];
        float* scb  = &sBuf[4224];     // 64
        float* sh   = &sBuf[4288];     // 8 warps * 2 nodes * 64 = 1024

        {
            const float4* wd = (const float4*)Wd1;
            const float4* wi = (const float4*)Wi1;
            float4* swd = (float4*)sWd1;
            float4* swi = (float4*)sWi1;
            swd[t] = wd[t]; swd[t + 256] = wd[t + 256];
            swi[t] = wi[t]; swi[t + 256] = wi[t + 256];
        }
        if (t < 32) { sWd2[t] = Wd2[t]; sWi2[t] = Wi2[t]; sbd1[t] = bd1[t]; sbi1[t] = bi1[t]; }
        if (t < 64) scb[t] = conv_b[128 + t];
        __syncthreads();

        int w = t >> 5, lane = t & 31;
        int nw = (t >> 4) & 1;
        int c4 = (t & 15) * 4;
        float bd2v = bd2[0], bi2v = bi2[0];
        float* shw = &sh[w * 128];

        for (int tile = bid; tile * tileN < N; tile += nb) {
            int lo = tile * tileN;
            int hiN = min(N, lo + tileN);
            for (int base = lo; base < hiN; base += 16) {
                int i = base + (t >> 4);
                float4 a = make_float4(0.f, 0.f, 0.f, 0.f);
                if (i < hiN) {
                    a = agg_node(g_hw0, i, c4);
                    a.x = fmaxf(a.x + scb[c4 + 0], 0.f);
                    a.y = fmaxf(a.y + scb[c4 + 1], 0.f);
                    a.z = fmaxf(a.z + scb[c4 + 2], 0.f);
                    a.w = fmaxf(a.w + scb[c4 + 3], 0.f);
                }
                float* s = &shw[nw * 64 + c4];
                s[0] = a.x; s[1] = a.y; s[2] = a.z; s[3] = a.w;
                __syncwarp();

                float ad0 = sbd1[lane], ai0 = sbi1[lane];
                float ad1 = sbd1[lane], ai1 = sbi1[lane];
#pragma unroll 16
                for (int k = 0; k < 64; k++) {
                    float h0 = shw[k];
                    float h1 = shw[64 + k];
                    float wd = sWd1[k * 32 + lane];
                    float wi = sWi1[k * 32 + lane];
                    ad0 += h0 * wd; ai0 += h0 * wi;
                    ad1 += h1 * wd; ai1 += h1 * wi;
                }
                float vd0 = fmaxf(ad0, 0.f) * sWd2[lane];
                float vi0 = fmaxf(ai0, 0.f) * sWi2[lane];
                float vd1 = fmaxf(ad1, 0.f) * sWd2[lane];
                float vi1 = fmaxf(ai1, 0.f) * sWi2[lane];
#pragma unroll
                for (int o = 16; o > 0; o >>= 1) {
                    vd0 += __shfl_xor_sync(0xffffffffu, vd0, o);
                    vi0 += __shfl_xor_sync(0xffffffffu, vi0, o);
                    vd1 += __shfl_xor_sync(0xffffffffu, vd1, o);
                    vi1 += __shfl_xor_sync(0xffffffffu, vi1, o);
                }
                int i0 = base + 2 * w;
                if (lane == 0 && i0 < hiN) {
                    out[i0]     = vd0 + bd2v;
                    out[N + i0] = vi0 + bi2v;
                    int i1 = i0 + 1;
                    if (i1 < hiN) {
                        out[i1]     = vd1 + bd2v;
                        out[N + i1] = vi1 + bi2v;
                    }
                }
                __syncwarp();
            }
        }
    }
}

// ---------------- launch ----------------
extern "C" void kernel_launch(void* const* d_in, const int* in_sizes, int n_in,
                              void* d_out, int out_size)
{
    const float* x      = (const float*)d_in[0];
    const int*   ei     = (const int*)d_in[1];     // int32 (JAX x64 off)
    const float* W_enc  = (const float*)d_in[2];
    const float* b_enc  = (const float*)d_in[3];
    const float* conv_W = (const float*)d_in[4];
    const float* conv_b = (const float*)d_in[5];
    const float* W_d1   = (const float*)d_in[6];
    const float* b_d1   = (const float*)d_in[7];
    const float* W_d2   = (const float*)d_in[8];
    const float* b_d2   = (const float*)d_in[9];
    const float* W_i1   = (const float*)d_in[10];
    const float* b_i1   = (const float*)d_in[11];
    const float* W_i2   = (const float*)d_in[12];
    const float* b_i2   = (const float*)d_in[13];
    float* out = (float*)d_out;

    int N = in_sizes[0] / 5;
    int E = in_sizes[1] / 2;
    const int* src = ei;
    const int* dst = ei + E;

    int dev = 0;
    cudaGetDevice(&dev);
    int sms = 148;
    cudaDeviceGetAttribute(&sms, cudaDevAttrMultiProcessorCount, dev);
    int bpm = 0;
    cudaOccupancyMaxActiveBlocksPerMultiprocessor(&bpm, persistent_k, 256, 0);
    if (bpm < 1) bpm = 1;
    if (bpm > 4) bpm = 4;
    int nb = sms * bpm;
    if (nb > 2048) nb = 2048;

    // exact partition: one tile per block (rounded even, capped by smem)
    int tileN = (N + nb - 1) / nb;
    tileN = (tileN + 1) & ~1;
    if (tileN < 2) tileN = 2;
    if (tileN > MAXTILE) tileN = MAXTILE;   // fallback loop handles leftovers

    persistent_k<<<nb, 256>>>(x, src, dst, W_enc, b_enc, conv_W, conv_b,
                              W_d1, b_d1, W_d2, b_d2,
                              W_i1, b_i1, W_i2, b_i2,
                              out, N, E, nb, tileN);
}